// round 1
// baseline (speedup 1.0000x reference)
#include <cuda_runtime.h>
#include <math_constants.h>

// ---------------------------------------------------------------------------
// CasualAttention: out = softmax(mask((x Wq)(x Wk)^T / sqrt(d))) (x Wv)
// Shapes: x[4,2048,1024], W*[1024,1024], out[4,2048,1024] fp32
// ---------------------------------------------------------------------------

#define BATCH 4
#define SEQ   2048
#define DIM   1024
#define MROWS (BATCH * SEQ)          // 8192

#define BM 128
#define BN 128
#define BK 16
#define TM 8
#define TN 8
#define NTHREADS 256

// Scratch (static device globals: allocation-guard safe)
__device__ float g_Q[BATCH * SEQ * DIM];   // 32 MB
__device__ float g_K[BATCH * SEQ * DIM];   // 32 MB
__device__ float g_V[BATCH * SEQ * DIM];   // 32 MB
__device__ float g_S[(size_t)BATCH * SEQ * SEQ]; // 64 MB (scores -> probs in place)

// ---------------------------------------------------------------------------
// Shared GEMM tile engine: computes a BMxBN tile of A*B (or A*B^T).
//   A: row-major [*, lda], tile rows start at m0
//   TRANS_B=false: B row-major [K, ldb], tile cols start at n0   (C = A B)
//   TRANS_B=true : B row-major [N, ldb], tile rows start at n0   (C = A B^T)
// kBegin/kEnd multiples of BK. All tile dims assumed in-bounds (true here).
// ---------------------------------------------------------------------------
template <bool TRANS_B>
__device__ __forceinline__ void gemm_tile(
    const float* __restrict__ A, int lda,
    const float* __restrict__ B, int ldb,
    int m0, int n0, int kBegin, int kEnd,
    float acc[TM][TN])
{
    __shared__ float As[BK][BM];
    __shared__ float Bs[BK][BN];

    const int t  = threadIdx.x;
    const int tx = t & 15;        // 0..15 -> n within tile
    const int ty = t >> 4;        // 0..15 -> m within tile

    #pragma unroll
    for (int i = 0; i < TM; i++)
        #pragma unroll
        for (int j = 0; j < TN; j++)
            acc[i][j] = 0.0f;

    for (int k0 = kBegin; k0 < kEnd; k0 += BK) {
        // --- load A tile: 128 rows x 16 k = 512 float4, 2 per thread, transpose ---
        #pragma unroll
        for (int i = 0; i < 2; i++) {
            int f   = t + i * NTHREADS;         // 0..511
            int row = f >> 2;                   // 0..127
            int kc  = (f & 3) << 2;             // 0,4,8,12
            float4 v = *reinterpret_cast<const float4*>(
                A + (size_t)(m0 + row) * lda + k0 + kc);
            As[kc + 0][row] = v.x;
            As[kc + 1][row] = v.y;
            As[kc + 2][row] = v.z;
            As[kc + 3][row] = v.w;
        }
        // --- load B tile ---
        if (TRANS_B) {
            // B rows are the N dim: [128 n][16 k], transpose into Bs[k][n]
            #pragma unroll
            for (int i = 0; i < 2; i++) {
                int f   = t + i * NTHREADS;
                int row = f >> 2;               // n within tile
                int kc  = (f & 3) << 2;
                float4 v = *reinterpret_cast<const float4*>(
                    B + (size_t)(n0 + row) * ldb + k0 + kc);
                Bs[kc + 0][row] = v.x;
                Bs[kc + 1][row] = v.y;
                Bs[kc + 2][row] = v.z;
                Bs[kc + 3][row] = v.w;
            }
        } else {
            // B: [16 k][128 n], copy straight through
            #pragma unroll
            for (int i = 0; i < 2; i++) {
                int f   = t + i * NTHREADS;
                int row = f >> 5;               // 0..15 (k)
                int c4  = (f & 31) << 2;        // 0..124 (n, float4 granules)
                *reinterpret_cast<float4*>(&Bs[row][c4]) =
                    *reinterpret_cast<const float4*>(
                        B + (size_t)(k0 + row) * ldb + n0 + c4);
            }
        }
        __syncthreads();

        #pragma unroll
        for (int kk = 0; kk < BK; kk++) {
            float4 a0 = *reinterpret_cast<const float4*>(&As[kk][ty * TM]);
            float4 a1 = *reinterpret_cast<const float4*>(&As[kk][ty * TM + 4]);
            float4 b0 = *reinterpret_cast<const float4*>(&Bs[kk][tx * TN]);
            float4 b1 = *reinterpret_cast<const float4*>(&Bs[kk][tx * TN + 4]);
            float a[TM] = {a0.x, a0.y, a0.z, a0.w, a1.x, a1.y, a1.z, a1.w};
            float b[TN] = {b0.x, b0.y, b0.z, b0.w, b1.x, b1.y, b1.z, b1.w};
            #pragma unroll
            for (int i = 0; i < TM; i++)
                #pragma unroll
                for (int j = 0; j < TN; j++)
                    acc[i][j] = fmaf(a[i], b[j], acc[i][j]);
        }
        __syncthreads();
    }
}

// ---------------------------------------------------------------------------
// Kernel 1: fused QKV projection. grid (DIM/BN, MROWS/BM, 3)
// ---------------------------------------------------------------------------
__global__ __launch_bounds__(NTHREADS)
void proj_kernel(const float* __restrict__ x,
                 const float* __restrict__ Wq,
                 const float* __restrict__ Wk,
                 const float* __restrict__ Wv)
{
    const float* W;
    float* out;
    if (blockIdx.z == 0)      { W = Wq; out = g_Q; }
    else if (blockIdx.z == 1) { W = Wk; out = g_K; }
    else                      { W = Wv; out = g_V; }

    const int m0 = blockIdx.y * BM;
    const int n0 = blockIdx.x * BN;

    float acc[TM][TN];
    gemm_tile<false>(x, DIM, W, DIM, m0, n0, 0, DIM, acc);

    const int tx = threadIdx.x & 15, ty = threadIdx.x >> 4;
    #pragma unroll
    for (int i = 0; i < TM; i++) {
        float* p = out + (size_t)(m0 + ty * TM + i) * DIM + n0 + tx * TN;
        *reinterpret_cast<float4*>(p)     = make_float4(acc[i][0], acc[i][1], acc[i][2], acc[i][3]);
        *reinterpret_cast<float4*>(p + 4) = make_float4(acc[i][4], acc[i][5], acc[i][6], acc[i][7]);
    }
}

// ---------------------------------------------------------------------------
// Kernel 2: S = Q K^T * scale with causal mask. grid (SEQ/BN, SEQ/BM, BATCH)
// Skips tiles fully above the diagonal (softmax/PV never read them).
// ---------------------------------------------------------------------------
__global__ __launch_bounds__(NTHREADS)
void qk_kernel()
{
    const int b  = blockIdx.z;
    const int q0 = blockIdx.y * BM;   // query tile
    const int k0 = blockIdx.x * BN;   // key tile
    if (k0 > q0 + BM - 1) return;     // fully masked tile

    const float* Q  = g_Q + (size_t)b * SEQ * DIM;
    const float* Km = g_K + (size_t)b * SEQ * DIM;
    float*       S  = g_S + (size_t)b * SEQ * SEQ;

    float acc[TM][TN];
    gemm_tile<true>(Q, DIM, Km, DIM, q0, k0, 0, DIM, acc);

    const float scale = 0.03125f;     // 1/sqrt(1024)
    const int tx = threadIdx.x & 15, ty = threadIdx.x >> 4;
    #pragma unroll
    for (int i = 0; i < TM; i++) {
        const int q = q0 + ty * TM + i;
        float v[TN];
        #pragma unroll
        for (int j = 0; j < TN; j++) {
            const int k = k0 + tx * TN + j;
            v[j] = (k <= q) ? acc[i][j] * scale : -CUDART_INF_F;
        }
        float* p = S + (size_t)q * SEQ + k0 + tx * TN;
        *reinterpret_cast<float4*>(p)     = make_float4(v[0], v[1], v[2], v[3]);
        *reinterpret_cast<float4*>(p + 4) = make_float4(v[4], v[5], v[6], v[7]);
    }
}

// ---------------------------------------------------------------------------
// Kernel 3: in-place causal row softmax. grid (BATCH*SEQ), 256 threads/row.
// Only reads j <= q; zeroes (q, tileEnd) so PV can run dense to the rounded
// causal boundary.
// ---------------------------------------------------------------------------
__global__ __launch_bounds__(NTHREADS)
void softmax_kernel()
{
    const int b = blockIdx.x >> 11;           // / SEQ
    const int q = blockIdx.x & (SEQ - 1);
    float* row = g_S + ((size_t)b * SEQ + q) * SEQ;
    const int L = q + 1;

    const int tid  = threadIdx.x;
    const int lane = tid & 31, warp = tid >> 5;
    __shared__ float redA[8], redB[8];

    // --- max ---
    float m = -CUDART_INF_F;
    for (int j = tid; j < L; j += NTHREADS) m = fmaxf(m, row[j]);
    #pragma unroll
    for (int o = 16; o; o >>= 1) m = fmaxf(m, __shfl_xor_sync(0xFFFFFFFFu, m, o));
    if (lane == 0) redA[warp] = m;
    __syncthreads();
    if (tid == 0) {
        float mm = redA[0];
        #pragma unroll
        for (int i = 1; i < 8; i++) mm = fmaxf(mm, redA[i]);
        redA[0] = mm;
    }
    __syncthreads();
    m = redA[0];

    // --- exp + sum ---
    float s = 0.0f;
    for (int j = tid; j < L; j += NTHREADS) {
        float e = __expf(row[j] - m);
        row[j] = e;
        s += e;
    }
    #pragma unroll
    for (int o = 16; o; o >>= 1) s += __shfl_xor_sync(0xFFFFFFFFu, s, o);
    if (lane == 0) redB[warp] = s;
    __syncthreads();
    if (tid == 0) {
        float ss = redB[0];
        #pragma unroll
        for (int i = 1; i < 8; i++) ss += redB[i];
        redB[0] = ss;
    }
    __syncthreads();
    const float inv = 1.0f / redB[0];

    for (int j = tid; j < L; j += NTHREADS) row[j] *= inv;

    // zero the masked tail of the diagonal 128-tile (PV reads up to tileEnd)
    const int tileEnd = ((q >> 7) + 1) << 7;
    for (int j = L + tid; j < tileEnd; j += NTHREADS) row[j] = 0.0f;
}

// ---------------------------------------------------------------------------
// Kernel 4: O = P V, k-loop ends at the causal tile boundary.
// grid (DIM/BN, SEQ/BM, BATCH)
// ---------------------------------------------------------------------------
__global__ __launch_bounds__(NTHREADS)
void pv_kernel(float* __restrict__ out)
{
    const int b  = blockIdx.z;
    const int q0 = blockIdx.y * BM;
    const int n0 = blockIdx.x * BN;

    const float* P = g_S + (size_t)b * SEQ * SEQ;
    const float* V = g_V + (size_t)b * SEQ * DIM;
    float*       O = out + (size_t)b * SEQ * DIM;

    const int kEnd = q0 + BM;   // causal boundary, multiple of BK

    float acc[TM][TN];
    gemm_tile<false>(P, SEQ, V, DIM, q0, n0, 0, kEnd, acc);

    const int tx = threadIdx.x & 15, ty = threadIdx.x >> 4;
    #pragma unroll
    for (int i = 0; i < TM; i++) {
        float* p = O + (size_t)(q0 + ty * TM + i) * DIM + n0 + tx * TN;
        *reinterpret_cast<float4*>(p)     = make_float4(acc[i][0], acc[i][1], acc[i][2], acc[i][3]);
        *reinterpret_cast<float4*>(p + 4) = make_float4(acc[i][4], acc[i][5], acc[i][6], acc[i][7]);
    }
}

// ---------------------------------------------------------------------------
extern "C" void kernel_launch(void* const* d_in, const int* in_sizes, int n_in,
                              void* d_out, int out_size)
{
    const float* x  = (const float*)d_in[0];
    const float* Wq = (const float*)d_in[1];
    const float* Wk = (const float*)d_in[2];
    const float* Wv = (const float*)d_in[3];
    float* out = (float*)d_out;

    proj_kernel<<<dim3(DIM / BN, MROWS / BM, 3), NTHREADS>>>(x, Wq, Wk, Wv);
    qk_kernel<<<dim3(SEQ / BN, SEQ / BM, BATCH), NTHREADS>>>();
    softmax_kernel<<<BATCH * SEQ, NTHREADS>>>();
    pv_kernel<<<dim3(DIM / BN, SEQ / BM, BATCH), NTHREADS>>>(out);
}

// round 6
// speedup vs baseline: 1.3721x; 1.3721x over previous
#include <cuda_runtime.h>
#include <math_constants.h>
#include <cstdint>

// ===========================================================================
// CasualAttention via tf32 mma.sync (m16n8k8) + cp.async pipeline, sm_103
//   x[4,2048,1024] fp32, W*[1024,1024] fp32 -> out[4,2048,1024] fp32
// All GEMMs NT: D[m,n] = sum_k A[m,k] * B[n,k]  (A,B row-major K-contiguous)
// Stages: round(x), W^T(rounded) -> proj QKV -> V^T(rounded)
//         -> QK^T (scale+mask) -> causal softmax (rounded) -> PV -> out
// ===========================================================================

#define BATCH 4
#define SEQ   2048
#define DIM   1024
#define MROWS (BATCH * SEQ)

#define BM 128
#define BN 128
#define BK 32
#define KPAD 36                       // row stride in floats (144B, 16B-aligned)
#define NSTAGES 3
#define STAGE_F (2 * BM * KPAD)       // floats per stage: A tile then B tile
#define SMEM_BYTES (NSTAGES * STAGE_F * 4)   // 110592

// ---------------- scratch (static device globals) --------------------------
__device__ float g_Xr[MROWS * DIM];              // rounded x
__device__ float g_Wt[3 * DIM * DIM];            // W^T rounded
__device__ float g_Q[MROWS * DIM];               // rounded
__device__ float g_K[MROWS * DIM];               // rounded
__device__ float g_V[MROWS * DIM];               // plain
__device__ float g_Vt[MROWS * DIM];              // V^T rounded [b][DIM][SEQ]
__device__ float g_S[(size_t)BATCH * SEQ * SEQ]; // scores -> probs in place

// ---------------- helpers ---------------------------------------------------
__device__ __forceinline__ uint32_t smem_u32(const void* p) {
    uint32_t a;
    asm("{ .reg .u64 t; cvta.to.shared.u64 t, %1; cvt.u32.u64 %0, t; }"
        : "=r"(a) : "l"(p));
    return a;
}
__device__ __forceinline__ float rna_tf32(float x) {
    float r;
    asm("cvt.rna.tf32.f32 %0, %1;" : "=f"(r) : "f"(x));
    return r;
}
__device__ __forceinline__ void cp16(float* dst, const float* src) {
    uint32_t d = smem_u32(dst);
    asm volatile("cp.async.cg.shared.global [%0], [%1], 16;" :: "r"(d), "l"(src));
}
#define CP_COMMIT() asm volatile("cp.async.commit_group;" ::: "memory")
#define CP_WAIT1()  asm volatile("cp.async.wait_group 1;"  ::: "memory")

__device__ __forceinline__ void mma8(float d[4], const float a[4], const float b[2]) {
    asm volatile(
        "mma.sync.aligned.m16n8k8.row.col.f32.tf32.tf32.f32 "
        "{%0,%1,%2,%3}, {%4,%5,%6,%7}, {%8,%9}, {%0,%1,%2,%3};"
        : "+f"(d[0]), "+f"(d[1]), "+f"(d[2]), "+f"(d[3])
        : "r"(__float_as_uint(a[0])), "r"(__float_as_uint(a[1])),
          "r"(__float_as_uint(a[2])), "r"(__float_as_uint(a[3])),
          "r"(__float_as_uint(b[0])), "r"(__float_as_uint(b[1])));
}

// ---------------- GEMM mainloop ---------------------------------------------
// 128 threads = 4 warps in 2x2 grid; each warp computes 64x64.
// acc[mf][nf][4] per mma.m16n8 fragment.
__device__ __forceinline__ void load_stage(float* stage,
                                           const float* __restrict__ A, int lda,
                                           const float* __restrict__ B, int ldb)
{
    const int r = threadIdx.x;                // 0..127 (row of A tile and B tile)
    const float* a = A + (size_t)r * lda;
    const float* b = B + (size_t)r * ldb;
    float* da = stage + r * KPAD;
    float* db = stage + BM * KPAD + r * KPAD;
    #pragma unroll
    for (int c = 0; c < 8; c++) cp16(da + c * 4, a + c * 4);
    #pragma unroll
    for (int c = 0; c < 8; c++) cp16(db + c * 4, b + c * 4);
}

__device__ __forceinline__ void gemm_main(const float* __restrict__ A, int lda,
                                          const float* __restrict__ B, int ldb,
                                          int kIters, float acc[4][8][4])
{
    extern __shared__ float smem[];
    const int wid  = threadIdx.x >> 5;
    const int lane = threadIdx.x & 31;
    const int g  = lane >> 2;
    const int tg = lane & 3;
    const int wm = (wid >> 1) * 64;
    const int wn = (wid & 1) * 64;

    // prologue: fill NSTAGES-1 stages (kIters >= 4 always here)
    #pragma unroll
    for (int s = 0; s < NSTAGES - 1; s++) {
        load_stage(smem + s * STAGE_F, A + s * BK, lda, B + s * BK, ldb);
        CP_COMMIT();
    }

    int slot = 0;
    for (int it = 0; it < kIters; it++) {
        CP_WAIT1();
        __syncthreads();

        const int nk = it + NSTAGES - 1;
        if (nk < kIters) {
            int ns = nk % NSTAGES;
            load_stage(smem + ns * STAGE_F, A + nk * BK, lda, B + nk * BK, ldb);
        }
        CP_COMMIT();

        const float* sA = smem + slot * STAGE_F + (wm + g) * KPAD;
        const float* sB = smem + slot * STAGE_F + BM * KPAD + (wn + g) * KPAD;

        #pragma unroll
        for (int ks = 0; ks < BK / 8; ks++) {
            const int col = ks * 8 + tg;
            float a[4][4];
            #pragma unroll
            for (int mf = 0; mf < 4; mf++) {
                const float* p = sA + mf * 16 * KPAD;
                a[mf][0] = p[col];
                a[mf][1] = p[8 * KPAD + col];
                a[mf][2] = p[col + 4];
                a[mf][3] = p[8 * KPAD + col + 4];
            }
            float b[8][2];
            #pragma unroll
            for (int nf = 0; nf < 8; nf++) {
                const float* p = sB + nf * 8 * KPAD;
                b[nf][0] = p[col];
                b[nf][1] = p[col + 4];
            }
            #pragma unroll
            for (int mf = 0; mf < 4; mf++)
                #pragma unroll
                for (int nf = 0; nf < 8; nf++)
                    mma8(acc[mf][nf], a[mf], b[nf]);
        }
        if (++slot == NSTAGES) slot = 0;
    }
}

#define ZERO_ACC(acc) do { \
    _Pragma("unroll") for (int _i = 0; _i < 4; _i++) \
    _Pragma("unroll") for (int _j = 0; _j < 8; _j++) \
    _Pragma("unroll") for (int _l = 0; _l < 4; _l++) acc[_i][_j][_l] = 0.0f; \
} while (0)

// ---------------- GEMM kernels ----------------------------------------------
__global__ __launch_bounds__(128, 2)
void proj_kernel()
{
    const int z  = blockIdx.z;
    const int m0 = blockIdx.y * BM;
    const int n0 = blockIdx.x * BN;
    const float* A = g_Xr + (size_t)m0 * DIM;
    const float* B = g_Wt + (size_t)z * DIM * DIM + (size_t)n0 * DIM;

    float acc[4][8][4];
    ZERO_ACC(acc);
    gemm_main(A, DIM, B, DIM, DIM / BK, acc);

    float* out = (z == 0) ? g_Q : (z == 1) ? g_K : g_V;
    const bool doRna = (z != 2);
    const int wid = threadIdx.x >> 5, lane = threadIdx.x & 31;
    const int g = lane >> 2, tg = lane & 3;
    const int rb = m0 + (wid >> 1) * 64 + g;
    const int cb = n0 + (wid & 1) * 64 + 2 * tg;
    #pragma unroll
    for (int mf = 0; mf < 4; mf++)
        #pragma unroll
        for (int nf = 0; nf < 8; nf++) {
            float v0 = acc[mf][nf][0], v1 = acc[mf][nf][1];
            float v2 = acc[mf][nf][2], v3 = acc[mf][nf][3];
            if (doRna) { v0 = rna_tf32(v0); v1 = rna_tf32(v1); v2 = rna_tf32(v2); v3 = rna_tf32(v3); }
            float* p0 = out + (size_t)(rb + mf * 16) * DIM + cb + nf * 8;
            float* p1 = out + (size_t)(rb + mf * 16 + 8) * DIM + cb + nf * 8;
            *reinterpret_cast<float2*>(p0) = make_float2(v0, v1);
            *reinterpret_cast<float2*>(p1) = make_float2(v2, v3);
        }
}

__global__ __launch_bounds__(128, 2)
void qk_kernel()
{
    const int b  = blockIdx.z;
    const int q0 = blockIdx.y * BM;
    const int k0 = blockIdx.x * BN;
    if (k0 > q0) return;                      // tile fully above diagonal

    const float* A = g_Q + (size_t)b * SEQ * DIM + (size_t)q0 * DIM;
    const float* B = g_K + (size_t)b * SEQ * DIM + (size_t)k0 * DIM;

    float acc[4][8][4];
    ZERO_ACC(acc);
    gemm_main(A, DIM, B, DIM, DIM / BK, acc);

    float* S = g_S + (size_t)b * SEQ * SEQ;
    const float scale = 0.03125f;             // 1/sqrt(1024)
    const int wid = threadIdx.x >> 5, lane = threadIdx.x & 31;
    const int g = lane >> 2, tg = lane & 3;
    const int rb = q0 + (wid >> 1) * 64 + g;
    const int cb = k0 + (wid & 1) * 64 + 2 * tg;
    #pragma unroll
    for (int mf = 0; mf < 4; mf++)
        #pragma unroll
        for (int nf = 0; nf < 8; nf++) {
            const int r0 = rb + mf * 16, r1 = r0 + 8;
            const int c  = cb + nf * 8;
            float v0 = (c     <= r0) ? acc[mf][nf][0] * scale : -CUDART_INF_F;
            float v1 = (c + 1 <= r0) ? acc[mf][nf][1] * scale : -CUDART_INF_F;
            float v2 = (c     <= r1) ? acc[mf][nf][2] * scale : -CUDART_INF_F;
            float v3 = (c + 1 <= r1) ? acc[mf][nf][3] * scale : -CUDART_INF_F;
            *reinterpret_cast<float2*>(S + (size_t)r0 * SEQ + c) = make_float2(v0, v1);
            *reinterpret_cast<float2*>(S + (size_t)r1 * SEQ + c) = make_float2(v2, v3);
        }
}

__global__ __launch_bounds__(128, 2)
void pv_kernel(float* __restrict__ out)
{
    const int b  = blockIdx.z;
    const int q0 = blockIdx.y * BM;
    const int n0 = blockIdx.x * BN;

    const float* A = g_S  + (size_t)b * SEQ * SEQ + (size_t)q0 * SEQ;
    const float* B = g_Vt + (size_t)b * DIM * SEQ + (size_t)n0 * SEQ;

    float acc[4][8][4];
    ZERO_ACC(acc);
    gemm_main(A, SEQ, B, SEQ, (q0 + BM) / BK, acc);   // causal k-bound

    float* O = out + (size_t)b * SEQ * DIM;
    const int wid = threadIdx.x >> 5, lane = threadIdx.x & 31;
    const int g = lane >> 2, tg = lane & 3;
    const int rb = q0 + (wid >> 1) * 64 + g;
    const int cb = n0 + (wid & 1) * 64 + 2 * tg;
    #pragma unroll
    for (int mf = 0; mf < 4; mf++)
        #pragma unroll
        for (int nf = 0; nf < 8; nf++) {
            float* p0 = O + (size_t)(rb + mf * 16) * DIM + cb + nf * 8;
            float* p1 = O + (size_t)(rb + mf * 16 + 8) * DIM + cb + nf * 8;
            *reinterpret_cast<float2*>(p0) = make_float2(acc[mf][nf][0], acc[mf][nf][1]);
            *reinterpret_cast<float2*>(p1) = make_float2(acc[mf][nf][2], acc[mf][nf][3]);
        }
}

// ---------------- prep kernels ----------------------------------------------
__global__ __launch_bounds__(256)
void round_x_kernel(const float* __restrict__ x)
{
    size_t i = ((size_t)blockIdx.x * 256 + threadIdx.x) * 4;
    float4 v = *reinterpret_cast<const float4*>(x + i);
    v.x = rna_tf32(v.x); v.y = rna_tf32(v.y); v.z = rna_tf32(v.z); v.w = rna_tf32(v.w);
    *reinterpret_cast<float4*>(g_Xr + i) = v;
}

__global__ __launch_bounds__(256)
void transpose_w_kernel(const float* __restrict__ Wq,
                        const float* __restrict__ Wk,
                        const float* __restrict__ Wv)
{
    __shared__ float t[32][33];
    const float* W = (blockIdx.z == 0) ? Wq : (blockIdx.z == 1) ? Wk : Wv;
    float* out = g_Wt + (size_t)blockIdx.z * DIM * DIM;
    const int n0 = blockIdx.x * 32, k0 = blockIdx.y * 32;
    const int tx = threadIdx.x & 31, ty = threadIdx.x >> 5;
    #pragma unroll
    for (int i = 0; i < 32; i += 8)
        t[ty + i][tx] = W[(size_t)(k0 + ty + i) * DIM + n0 + tx];
    __syncthreads();
    #pragma unroll
    for (int i = 0; i < 32; i += 8)
        out[(size_t)(n0 + ty + i) * DIM + k0 + tx] = rna_tf32(t[tx][ty + i]);
}

__global__ __launch_bounds__(256)
void transpose_v_kernel()
{
    __shared__ float t[32][33];
    const int b = blockIdx.z;
    const float* V = g_V + (size_t)b * SEQ * DIM;
    float* out = g_Vt + (size_t)b * DIM * SEQ;
    const int d0 = blockIdx.x * 32, s0 = blockIdx.y * 32;
    const int tx = threadIdx.x & 31, ty = threadIdx.x >> 5;
    #pragma unroll
    for (int i = 0; i < 32; i += 8)
        t[ty + i][tx] = V[(size_t)(s0 + ty + i) * DIM + d0 + tx];
    __syncthreads();
    #pragma unroll
    for (int i = 0; i < 32; i += 8)
        out[(size_t)(d0 + ty + i) * SEQ + s0 + tx] = rna_tf32(t[tx][ty + i]);
}

// ---------------- softmax (causal, in-place, rounded) -----------------------
__global__ __launch_bounds__(256)
void softmax_kernel()
{
    const int b = blockIdx.x >> 11;
    const int q = blockIdx.x & (SEQ - 1);
    float* row = g_S + ((size_t)b * SEQ + q) * SEQ;
    const int L = q + 1;

    const int tid = threadIdx.x, lane = tid & 31, warp = tid >> 5;
    __shared__ float redA[8], redB[8];

    float m = -CUDART_INF_F;
    for (int j = tid; j < L; j += 256) m = fmaxf(m, row[j]);
    #pragma unroll
    for (int o = 16; o; o >>= 1) m = fmaxf(m, __shfl_xor_sync(0xFFFFFFFFu, m, o));
    if (lane == 0) redA[warp] = m;
    __syncthreads();
    if (tid == 0) {
        float mm = redA[0];
        #pragma unroll
        for (int i = 1; i < 8; i++) mm = fmaxf(mm, redA[i]);
        redA[0] = mm;
    }
    __syncthreads();
    m = redA[0];

    float s = 0.0f;
    for (int j = tid; j < L; j += 256) {
        float e = __expf(row[j] - m);
        row[j] = e;
        s += e;
    }
    #pragma unroll
    for (int o = 16; o; o >>= 1) s += __shfl_xor_sync(0xFFFFFFFFu, s, o);
    if (lane == 0) redB[warp] = s;
    __syncthreads();
    if (tid == 0) {
        float ss = redB[0];
        #pragma unroll
        for (int i = 1; i < 8; i++) ss += redB[i];
        redB[0] = ss;
    }
    __syncthreads();
    const float inv = 1.0f / redB[0];

    for (int j = tid; j < L; j += 256) row[j] = rna_tf32(row[j] * inv);

    // zero the masked remainder of the diagonal 128-tile (PV reads it)
    const int tileEnd = ((q >> 7) + 1) << 7;
    for (int j = L + tid; j < tileEnd; j += 256) row[j] = 0.0f;
}

// ---------------- host side --------------------------------------------------
extern "C" void kernel_launch(void* const* d_in, const int* in_sizes, int n_in,
                              void* d_out, int out_size)
{
    const float* x  = (const float*)d_in[0];
    const float* Wq = (const float*)d_in[1];
    const float* Wk = (const float*)d_in[2];
    const float* Wv = (const float*)d_in[3];
    float* out = (float*)d_out;

    static bool configured = false;
    if (!configured) {
        cudaFuncSetAttribute(proj_kernel, cudaFuncAttributeMaxDynamicSharedMemorySize, SMEM_BYTES);
        cudaFuncSetAttribute(qk_kernel,   cudaFuncAttributeMaxDynamicSharedMemorySize, SMEM_BYTES);
        cudaFuncSetAttribute(pv_kernel,   cudaFuncAttributeMaxDynamicSharedMemorySize, SMEM_BYTES);
        configured = true;
    }

    round_x_kernel<<<MROWS * DIM / 1024, 256>>>(x);
    transpose_w_kernel<<<dim3(32, 32, 3), 256>>>(Wq, Wk, Wv);
    proj_kernel<<<dim3(DIM / BN, MROWS / BM, 3), 128, SMEM_BYTES>>>();
    transpose_v_kernel<<<dim3(DIM / 32, SEQ / 32, BATCH), 256>>>();
    qk_kernel<<<dim3(SEQ / BN, SEQ / BM, BATCH), 128, SMEM_BYTES>>>();
    softmax_kernel<<<BATCH * SEQ, 256>>>();
    pv_kernel<<<dim3(DIM / BN, SEQ / BM, BATCH), 128, SMEM_BYTES>>>(out);
}

// round 8
// speedup vs baseline: 4.1890x; 3.0529x over previous
#include <cuda_runtime.h>
#include <math_constants.h>
#include <cstdint>

// ===========================================================================
// CasualAttention via tf32 mma.sync (m16n8k8), fragment-packed operands.
//   x[4,2048,1024] fp32, W*[1024,1024] fp32 -> out[4,2048,1024] fp32
// All GEMMs NT: D[m,n] = sum_k A[m,k]*B[n,k].
// A operands packed as [mblk=M/16][kblk=K/8][lane32][reg4] (512B blocks)
//   lane=(r%8)*4+(c%4), reg=(r%16)/8 + 2*((c%8)/4)  == mma A-fragment order
// B operands packed as [nblk=N/8][kblk=K/8][lane32][reg2] (256B blocks)
//   lane=(n%8)*4+(k%4), reg=(k%8)/4                 == mma B-fragment order
// ===========================================================================

#define BATCH 4
#define SEQ   2048
#define DIM   1024
#define MROWS (BATCH * SEQ)

#define BM 128
#define BN 128
#define BK 32
#define NSTAGES 3
#define STAGE_F 8192                      // floats: A 4096 + B 4096
#define SMEM_BYTES (NSTAGES * STAGE_F * 4)   // 98304

// ---------------- scratch ---------------------------------------------------
__device__ float g_PAX[512 * 128 * 128];              // x packed-A   (32MB)
__device__ float g_PBW[3 * 128 * 128 * 64];           // W^T packed-B (12MB)
__device__ float g_PAQ[(size_t)BATCH * 128 * 128 * 128];   // Q packed-A
__device__ float g_PBK[(size_t)BATCH * 256 * 128 * 64];    // K packed-B
__device__ float g_V  [(size_t)MROWS * DIM];               // V normal
__device__ float g_PBV[(size_t)BATCH * 128 * 256 * 64];    // V^T packed-B
__device__ float g_PAS[(size_t)BATCH * 128 * 256 * 128];   // S/P packed-A (64MB)

// ---------------- helpers ---------------------------------------------------
__device__ __forceinline__ uint32_t smem_u32(const void* p) {
    uint32_t a;
    asm("{ .reg .u64 t; cvta.to.shared.u64 t, %1; cvt.u32.u64 %0, t; }"
        : "=r"(a) : "l"(p));
    return a;
}
__device__ __forceinline__ float rna_tf32(float x) {
    float r;
    asm("cvt.rna.tf32.f32 %0, %1;" : "=f"(r) : "f"(x));
    return r;
}
__device__ __forceinline__ void cp16(float* dst, const float* src) {
    uint32_t d = smem_u32(dst);
    asm volatile("cp.async.cg.shared.global [%0], [%1], 16;" :: "r"(d), "l"(src));
}
#define CP_COMMIT() asm volatile("cp.async.commit_group;" ::: "memory")
#define CP_WAIT1()  asm volatile("cp.async.wait_group 1;"  ::: "memory")

__device__ __forceinline__ void mma8(float d[4], float4 a, float2 b) {
    asm volatile(
        "mma.sync.aligned.m16n8k8.row.col.f32.tf32.tf32.f32 "
        "{%0,%1,%2,%3}, {%4,%5,%6,%7}, {%8,%9}, {%0,%1,%2,%3};"
        : "+f"(d[0]), "+f"(d[1]), "+f"(d[2]), "+f"(d[3])
        : "r"(__float_as_uint(a.x)), "r"(__float_as_uint(a.y)),
          "r"(__float_as_uint(a.z)), "r"(__float_as_uint(a.w)),
          "r"(__float_as_uint(b.x)), "r"(__float_as_uint(b.y)));
}

// packed-A float index within one matrix (kbTot = K/8)
__device__ __forceinline__ size_t paIdx(int kbTot, int r, int c) {
    return (((size_t)(r >> 4) * kbTot + (c >> 3)) << 7)
         + (((r & 7) << 2) + (c & 3)) * 4 + ((r >> 3) & 1) + (((c >> 2) & 1) << 1);
}
// packed-B float index (kbTot = K/8)
__device__ __forceinline__ size_t pbIdx(int kbTot, int n, int k) {
    return (((size_t)(n >> 3) * kbTot + (k >> 3)) << 6)
         + (((n & 7) << 2) + (k & 3)) * 2 + ((k >> 2) & 1);
}

// ---------------- GEMM mainloop ---------------------------------------------
// 128 threads = 4 warps (2x2); warp tile 64x64. Ab/Bb already offset to tile
// row/col start (block granularity). ka/kb = total kblks of each matrix.
__device__ __forceinline__ void load_stage(float* st,
                                           const float* __restrict__ Ab, int ka,
                                           const float* __restrict__ Bb, int kbt,
                                           int kb)
{
    const int t = threadIdx.x;
    {
        const int mb = t >> 4, c0 = t & 15;
        const float* src = Ab + ((size_t)mb * ka + kb) * 128;
        float* dst = st + mb * 512;
        #pragma unroll
        for (int j = 0; j < 8; j++)
            cp16(dst + (c0 + 16 * j) * 4, src + (c0 + 16 * j) * 4);
    }
    {
        const int nb = t >> 3, c0 = t & 7;
        const float* src = Bb + ((size_t)nb * kbt + kb) * 64;
        float* dst = st + 4096 + nb * 256;
        #pragma unroll
        for (int j = 0; j < 8; j++)
            cp16(dst + (c0 + 8 * j) * 4, src + (c0 + 8 * j) * 4);
    }
}

__device__ __forceinline__ void gemm_main(const float* __restrict__ Ab, int ka,
                                          const float* __restrict__ Bb, int kbt,
                                          int kIters, float acc[4][8][4])
{
    extern __shared__ float smem[];
    const int wid  = threadIdx.x >> 5;
    const int lane = threadIdx.x & 31;

    #pragma unroll
    for (int s = 0; s < NSTAGES - 1; s++) {
        load_stage(smem + s * STAGE_F, Ab, ka, Bb, kbt, s * 4);
        CP_COMMIT();
    }

    int slot = 0;
    for (int it = 0; it < kIters; it++) {
        CP_WAIT1();
        __syncthreads();

        const int nk = it + NSTAGES - 1;
        if (nk < kIters) {
            int ns = nk % NSTAGES;
            load_stage(smem + ns * STAGE_F, Ab, ka, Bb, kbt, nk * 4);
        }
        CP_COMMIT();

        const float* sA = smem + slot * STAGE_F + ((wid >> 1) * 4) * 512;
        const float* sB = smem + slot * STAGE_F + 4096 + ((wid & 1) * 8) * 256;

        #pragma unroll
        for (int ks = 0; ks < 4; ks++) {
            float4 av[4];
            #pragma unroll
            for (int mf = 0; mf < 4; mf++)
                av[mf] = *reinterpret_cast<const float4*>(sA + mf * 512 + ks * 128 + lane * 4);
            float2 bv[8];
            #pragma unroll
            for (int nf = 0; nf < 8; nf++)
                bv[nf] = *reinterpret_cast<const float2*>(sB + nf * 256 + ks * 64 + lane * 2);
            #pragma unroll
            for (int mf = 0; mf < 4; mf++)
                #pragma unroll
                for (int nf = 0; nf < 8; nf++)
                    mma8(acc[mf][nf], av[mf], bv[nf]);
        }
        if (++slot == NSTAGES) slot = 0;
    }
}

#define ZERO_ACC(acc) do { \
    _Pragma("unroll") for (int _i = 0; _i < 4; _i++) \
    _Pragma("unroll") for (int _j = 0; _j < 8; _j++) \
    _Pragma("unroll") for (int _l = 0; _l < 4; _l++) acc[_i][_j][_l] = 0.0f; \
} while (0)

// ---------------- GEMM kernels ----------------------------------------------
__global__ __launch_bounds__(128, 2)
void proj_kernel()
{
    const int z  = blockIdx.z;
    const int m0 = blockIdx.y * BM;          // global row 0..8191
    const int n0 = blockIdx.x * BN;          // 0..1023
    const float* Ab = g_PAX + ((size_t)(m0 >> 4) * 128) * 128;
    const float* Bb = g_PBW + ((size_t)(z * 128 + (n0 >> 3)) * 128) * 64;

    float acc[4][8][4];
    ZERO_ACC(acc);
    gemm_main(Ab, 128, Bb, 128, DIM / BK, acc);

    const int wid = threadIdx.x >> 5, lane = threadIdx.x & 31;
    const int g = lane >> 2, tg = lane & 3;
    const int rb = m0 + ((wid >> 1) << 6) + g;
    const int cb = n0 + ((wid & 1) << 6) + 2 * tg;
    const int b  = m0 >> 11;

    if (z == 0) {
        float* base = g_PAQ + (size_t)b * (128 * 128 * 128);
        #pragma unroll
        for (int mf = 0; mf < 4; mf++)
            #pragma unroll
            for (int nf = 0; nf < 8; nf++) {
                const int r = (rb + mf * 16) & 2047, c = cb + nf * 8;
                base[paIdx(128, r,     c    )] = rna_tf32(acc[mf][nf][0]);
                base[paIdx(128, r,     c + 1)] = rna_tf32(acc[mf][nf][1]);
                base[paIdx(128, r + 8, c    )] = rna_tf32(acc[mf][nf][2]);
                base[paIdx(128, r + 8, c + 1)] = rna_tf32(acc[mf][nf][3]);
            }
    } else if (z == 1) {
        float* base = g_PBK + (size_t)b * (256 * 128 * 64);
        #pragma unroll
        for (int mf = 0; mf < 4; mf++)
            #pragma unroll
            for (int nf = 0; nf < 8; nf++) {
                const int r = (rb + mf * 16) & 2047, c = cb + nf * 8;
                base[pbIdx(128, r,     c    )] = rna_tf32(acc[mf][nf][0]);
                base[pbIdx(128, r,     c + 1)] = rna_tf32(acc[mf][nf][1]);
                base[pbIdx(128, r + 8, c    )] = rna_tf32(acc[mf][nf][2]);
                base[pbIdx(128, r + 8, c + 1)] = rna_tf32(acc[mf][nf][3]);
            }
    } else {
        #pragma unroll
        for (int mf = 0; mf < 4; mf++)
            #pragma unroll
            for (int nf = 0; nf < 8; nf++) {
                float* p0 = g_V + (size_t)(rb + mf * 16) * DIM + cb + nf * 8;
                float* p1 = g_V + (size_t)(rb + mf * 16 + 8) * DIM + cb + nf * 8;
                *reinterpret_cast<float2*>(p0) = make_float2(acc[mf][nf][0], acc[mf][nf][1]);
                *reinterpret_cast<float2*>(p1) = make_float2(acc[mf][nf][2], acc[mf][nf][3]);
            }
    }
}

__global__ __launch_bounds__(128, 2)
void qk_kernel()
{
    const int b  = blockIdx.z;
    const int q0 = blockIdx.y * BM;
    const int k0 = blockIdx.x * BN;
    if (k0 > q0) return;

    const float* Ab = g_PAQ + (size_t)b * (128*128*128) + ((size_t)(q0 >> 4) * 128) * 128;
    const float* Bb = g_PBK + (size_t)b * (256*128*64)  + ((size_t)(k0 >> 3) * 128) * 64;

    float acc[4][8][4];
    ZERO_ACC(acc);
    gemm_main(Ab, 128, Bb, 128, DIM / BK, acc);

    float* base = g_PAS + (size_t)b * (128 * 256 * 128);
    const float scale = 0.03125f;
    const int wid = threadIdx.x >> 5, lane = threadIdx.x & 31;
    const int g = lane >> 2, tg = lane & 3;
    const int rb = q0 + ((wid >> 1) << 6) + g;
    const int cb = k0 + ((wid & 1) << 6) + 2 * tg;
    #pragma unroll
    for (int mf = 0; mf < 4; mf++)
        #pragma unroll
        for (int nf = 0; nf < 8; nf++) {
            const int r0 = rb + mf * 16, r1 = r0 + 8;
            const int c  = cb + nf * 8;
            base[paIdx(256, r0, c    )] = (c     <= r0) ? acc[mf][nf][0] * scale : -CUDART_INF_F;
            base[paIdx(256, r0, c + 1)] = (c + 1 <= r0) ? acc[mf][nf][1] * scale : -CUDART_INF_F;
            base[paIdx(256, r1, c    )] = (c     <= r1) ? acc[mf][nf][2] * scale : -CUDART_INF_F;
            base[paIdx(256, r1, c + 1)] = (c + 1 <= r1) ? acc[mf][nf][3] * scale : -CUDART_INF_F;
        }
}

__global__ __launch_bounds__(128, 2)
void pv_kernel(float* __restrict__ out)
{
    const int b  = blockIdx.z;
    const int q0 = blockIdx.y * BM;
    const int n0 = blockIdx.x * BN;

    const float* Ab = g_PAS + (size_t)b * (128*256*128) + ((size_t)(q0 >> 4) * 256) * 128;
    const float* Bb = g_PBV + (size_t)b * (128*256*64)  + ((size_t)(n0 >> 3) * 256) * 64;

    float acc[4][8][4];
    ZERO_ACC(acc);
    gemm_main(Ab, 256, Bb, 256, (q0 + BM) / BK, acc);

    float* O = out + (size_t)b * SEQ * DIM;
    const int wid = threadIdx.x >> 5, lane = threadIdx.x & 31;
    const int g = lane >> 2, tg = lane & 3;
    const int rb = q0 + ((wid >> 1) << 6) + g;
    const int cb = n0 + ((wid & 1) << 6) + 2 * tg;
    #pragma unroll
    for (int mf = 0; mf < 4; mf++)
        #pragma unroll
        for (int nf = 0; nf < 8; nf++) {
            float* p0 = O + (size_t)(rb + mf * 16) * DIM + cb + nf * 8;
            float* p1 = O + (size_t)(rb + mf * 16 + 8) * DIM + cb + nf * 8;
            *reinterpret_cast<float2*>(p0) = make_float2(acc[mf][nf][0], acc[mf][nf][1]);
            *reinterpret_cast<float2*>(p1) = make_float2(acc[mf][nf][2], acc[mf][nf][3]);
        }
}

// ---------------- pack kernels ----------------------------------------------
__global__ __launch_bounds__(256)
void pack_x_kernel(const float* __restrict__ x)
{
    __shared__ float sm[16][260];
    const int mb = blockIdx.x;              // 0..511 (16-row group of 8192)
    const int kc = blockIdx.y;              // 0..3 (256-col chunk)
    const float* src = x + (size_t)mb * 16 * DIM + kc * 256;
    for (int i = threadIdx.x; i < 1024; i += 256) {   // 16x256 floats as float4
        int row = i >> 6, c4 = i & 63;
        float4 v = *reinterpret_cast<const float4*>(src + (size_t)row * DIM + c4 * 4);
        *reinterpret_cast<float4*>(&sm[row][c4 * 4]) = v;
    }
    __syncthreads();
    #pragma unroll
    for (int j = 0; j < 4; j++) {
        int s = threadIdx.x + j * 256;      // 0..1023 = 32 kblk x 32 lanes
        int kbl = s >> 5, L = s & 31;
        int r8 = L >> 2, c4 = L & 3;
        float4 v;
        v.x = rna_tf32(sm[r8    ][kbl * 8 + c4    ]);
        v.y = rna_tf32(sm[r8 + 8][kbl * 8 + c4    ]);
        v.z = rna_tf32(sm[r8    ][kbl * 8 + c4 + 4]);
        v.w = rna_tf32(sm[r8 + 8][kbl * 8 + c4 + 4]);
        *reinterpret_cast<float4*>(
            g_PAX + ((size_t)(mb * 128 + kc * 32 + kbl)) * 128 + L * 4) = v;
    }
}

__global__ __launch_bounds__(256)
void pack_w_kernel(const float* __restrict__ Wq,
                   const float* __restrict__ Wk,
                   const float* __restrict__ Wv)
{
    int s = blockIdx.x * 256 + threadIdx.x;
    int L = s & 31, kblk = (s >> 5) & 127, nblk = (s >> 12) & 127, z = s >> 19;
    const float* W = (z == 0) ? Wq : (z == 1) ? Wk : Wv;
    int n = nblk * 8 + (L >> 2), k = kblk * 8 + (L & 3);
    float2 v;
    v.x = rna_tf32(W[(size_t)k * DIM + n]);
    v.y = rna_tf32(W[(size_t)(k + 4) * DIM + n]);
    *reinterpret_cast<float2*>(
        g_PBW + ((size_t)((z * 128 + nblk) * 128 + kblk)) * 64 + L * 2) = v;
}

__global__ __launch_bounds__(256)
void pack_v_kernel()
{
    int s = blockIdx.x * 256 + threadIdx.x;
    int L = s & 31, sblk = (s >> 5) & 255, dblk = (s >> 13) & 127, b = s >> 20;
    int d = dblk * 8 + (L >> 2), sq = sblk * 8 + (L & 3);
    const float* V = g_V + (size_t)b * SEQ * DIM;
    float2 v;
    v.x = rna_tf32(V[(size_t)sq * DIM + d]);
    v.y = rna_tf32(V[(size_t)(sq + 4) * DIM + d]);
    *reinterpret_cast<float2*>(
        g_PBV + ((size_t)((b * 128 + dblk) * 256 + sblk)) * 64 + L * 2) = v;
}

// ---------------- softmax on packed layout ----------------------------------
// CTA per (16-row group, batch). 2R + 1W, exp recomputed; zeroes masked tail
// blocks up to the 128-row causal boundary so PV runs dense.
__global__ __launch_bounds__(256)
void softmax_kernel()
{
    const int mblk = blockIdx.x;            // 0..127
    const int b    = blockIdx.y;
    float* base = g_PAS + (size_t)b * (128 * 256 * 128) + (size_t)mblk * 256 * 128;
    const int KB = 2 * mblk + 2;                     // blocks holding k <= m0+15
    const int ZB = ((mblk >> 3) << 4) + 16;          // causal boundary blocks

    const int t = threadIdx.x, kp = t >> 5, lane = t & 31;
    const int r0 = lane >> 2;
    __shared__ float red[16][33];
    __shared__ float rowmax[16], rowinv[16];

    float mlo = -CUDART_INF_F, mhi = -CUDART_INF_F;
    for (int kb = kp; kb < KB; kb += 8) {
        float4 f = *reinterpret_cast<const float4*>(base + kb * 128 + lane * 4);
        mlo = fmaxf(mlo, fmaxf(f.x, f.z));
        mhi = fmaxf(mhi, fmaxf(f.y, f.w));
    }
    red[r0][kp * 4 + (lane & 3)] = mlo;
    red[r0 + 8][kp * 4 + (lane & 3)] = mhi;
    __syncthreads();
    if (t < 16) {
        float m = -CUDART_INF_F;
        #pragma unroll
        for (int j = 0; j < 32; j++) m = fmaxf(m, red[t][j]);
        rowmax[t] = m;
    }
    __syncthreads();
    const float Mlo = rowmax[r0], Mhi = rowmax[r0 + 8];

    float slo = 0.0f, shi = 0.0f;
    for (int kb = kp; kb < KB; kb += 8) {
        float4 f = *reinterpret_cast<const float4*>(base + kb * 128 + lane * 4);
        slo += __expf(f.x - Mlo) + __expf(f.z - Mlo);
        shi += __expf(f.y - Mhi) + __expf(f.w - Mhi);
    }
    __syncthreads();
    red[r0][kp * 4 + (lane & 3)] = slo;
    red[r0 + 8][kp * 4 + (lane & 3)] = shi;
    __syncthreads();
    if (t < 16) {
        float ssum = 0.0f;
        #pragma unroll
        for (int j = 0; j < 32; j++) ssum += red[t][j];
        rowinv[t] = 1.0f / ssum;
    }
    __syncthreads();
    const float Ilo = rowinv[r0], Ihi = rowinv[r0 + 8];

    for (int kb = kp; kb < KB; kb += 8) {
        float4 f = *reinterpret_cast<float4*>(base + kb * 128 + lane * 4);
        f.x = rna_tf32(__expf(f.x - Mlo) * Ilo);
        f.z = rna_tf32(__expf(f.z - Mlo) * Ilo);
        f.y = rna_tf32(__expf(f.y - Mhi) * Ihi);
        f.w = rna_tf32(__expf(f.w - Mhi) * Ihi);
        *reinterpret_cast<float4*>(base + kb * 128 + lane * 4) = f;
    }

    // zero the masked blocks [KB, ZB) (read dense by PV)
    const int nz4 = (ZB - KB) * 32;
    float4 z4 = make_float4(0.f, 0.f, 0.f, 0.f);
    for (int i = t; i < nz4; i += 256)
        reinterpret_cast<float4*>(base + KB * 128)[i] = z4;
}

// ---------------- host side --------------------------------------------------
extern "C" void kernel_launch(void* const* d_in, const int* in_sizes, int n_in,
                              void* d_out, int out_size)
{
    const float* x  = (const float*)d_in[0];
    const float* Wq = (const float*)d_in[1];
    const float* Wk = (const float*)d_in[2];
    const float* Wv = (const float*)d_in[3];
    float* out = (float*)d_out;

    static bool configured = false;
    if (!configured) {
        cudaFuncSetAttribute(proj_kernel, cudaFuncAttributeMaxDynamicSharedMemorySize, SMEM_BYTES);
        cudaFuncSetAttribute(qk_kernel,   cudaFuncAttributeMaxDynamicSharedMemorySize, SMEM_BYTES);
        cudaFuncSetAttribute(pv_kernel,   cudaFuncAttributeMaxDynamicSharedMemorySize, SMEM_BYTES);
        configured = true;
    }

    pack_x_kernel<<<dim3(512, 4), 256>>>(x);
    pack_w_kernel<<<6144, 256>>>(Wq, Wk, Wv);
    proj_kernel<<<dim3(DIM / BN, MROWS / BM, 3), 128, SMEM_BYTES>>>();
    qk_kernel<<<dim3(SEQ / BN, SEQ / BM, BATCH), 128, SMEM_BYTES>>>();   // profiled idx 3
    pack_v_kernel<<<16384, 256>>>();
    softmax_kernel<<<dim3(128, BATCH), 256>>>();
    pv_kernel<<<dim3(DIM / BN, SEQ / BM, BATCH), 128, SMEM_BYTES>>>(out);
}

// round 9
// speedup vs baseline: 4.2389x; 1.0119x over previous
#include <cuda_runtime.h>
#include <math_constants.h>
#include <cstdint>

// ===========================================================================
// CasualAttention via tf32 mma.sync (m16n8k8), fragment-packed operands.
//   x[4,2048,1024] fp32, W*[1024,1024] fp32 -> out[4,2048,1024] fp32
// All GEMMs NT: D[m,n] = sum_k A[m,k]*B[n,k].
// A packed: [mblk=M/16][kblk=K/8][lane32][reg4] (512B blocks)
// B packed: [nblk=N/8][kblk=K/8][lane32][reg2] (256B blocks)
// 256 thr/CTA, 8 warps (2x4), warp tile 64x32.
// ===========================================================================

#define BATCH 4
#define SEQ   2048
#define DIM   1024
#define MROWS (BATCH * SEQ)

#define BM 128
#define BN 128
#define BK 32
#define NSTAGES 3
#define STAGE_F 8192                      // floats: A 4096 + B 4096
#define SMEM_BYTES (NSTAGES * STAGE_F * 4)   // 98304

// ---------------- scratch ---------------------------------------------------
__device__ float g_PAX[512 * 128 * 128];              // x packed-A   (32MB)
__device__ float g_PBW[3 * 128 * 128 * 64];           // W^T packed-B (12MB)
__device__ float g_PAQ[(size_t)BATCH * 128 * 128 * 128];   // Q packed-A
__device__ float g_PBK[(size_t)BATCH * 256 * 128 * 64];    // K packed-B
__device__ float g_PBV[(size_t)BATCH * 128 * 256 * 64];    // V^T packed-B
__device__ float g_PAS[(size_t)BATCH * 128 * 256 * 128];   // S/P packed-A (64MB)

// ---------------- helpers ---------------------------------------------------
__device__ __forceinline__ uint32_t smem_u32(const void* p) {
    uint32_t a;
    asm("{ .reg .u64 t; cvta.to.shared.u64 t, %1; cvt.u32.u64 %0, t; }"
        : "=r"(a) : "l"(p));
    return a;
}
__device__ __forceinline__ float rna_tf32(float x) {
    float r;
    asm("cvt.rna.tf32.f32 %0, %1;" : "=f"(r) : "f"(x));
    return r;
}
__device__ __forceinline__ void cp16(float* dst, const float* src) {
    uint32_t d = smem_u32(dst);
    asm volatile("cp.async.cg.shared.global [%0], [%1], 16;" :: "r"(d), "l"(src));
}
#define CP_COMMIT() asm volatile("cp.async.commit_group;" ::: "memory")
#define CP_WAIT1()  asm volatile("cp.async.wait_group 1;"  ::: "memory")

__device__ __forceinline__ void mma8(float d[4], float4 a, float2 b) {
    asm volatile(
        "mma.sync.aligned.m16n8k8.row.col.f32.tf32.tf32.f32 "
        "{%0,%1,%2,%3}, {%4,%5,%6,%7}, {%8,%9}, {%0,%1,%2,%3};"
        : "+f"(d[0]), "+f"(d[1]), "+f"(d[2]), "+f"(d[3])
        : "r"(__float_as_uint(a.x)), "r"(__float_as_uint(a.y)),
          "r"(__float_as_uint(a.z)), "r"(__float_as_uint(a.w)),
          "r"(__float_as_uint(b.x)), "r"(__float_as_uint(b.y)));
}

// packed-A float index within one matrix (kbTot = K/8)
__device__ __forceinline__ size_t paIdx(int kbTot, int r, int c) {
    return (((size_t)(r >> 4) * kbTot + (c >> 3)) << 7)
         + (((r & 7) << 2) + (c & 3)) * 4 + ((r >> 3) & 1) + (((c >> 2) & 1) << 1);
}
// packed-B float index (kbTot = K/8)
__device__ __forceinline__ size_t pbIdx(int kbTot, int n, int k) {
    return (((size_t)(n >> 3) * kbTot + (k >> 3)) << 6)
         + (((n & 7) << 2) + (k & 3)) * 2 + ((k >> 2) & 1);
}

// ---------------- GEMM mainloop ---------------------------------------------
// 256 threads = 8 warps (2x4); warp tile 64x32.
__device__ __forceinline__ void load_stage(float* st,
                                           const float* __restrict__ Ab, int ka,
                                           const float* __restrict__ Bb, int kbt,
                                           int kb0)
{
    const int t = threadIdx.x;
    #pragma unroll
    for (int j = 0; j < 4; j++) {          // A: 1024 float4
        int f = t + j * 256;
        int mb = f >> 7, r = f & 127, kb = r >> 5, li = r & 31;
        cp16(st + mb * 512 + kb * 128 + li * 4,
             Ab + ((size_t)mb * ka + kb0 + kb) * 128 + li * 4);
    }
    #pragma unroll
    for (int j = 0; j < 4; j++) {          // B: 1024 float4
        int f = t + j * 256;
        int nb = f >> 6, r = f & 63, kb = r >> 4, li = r & 15;
        cp16(st + 4096 + nb * 256 + kb * 64 + li * 4,
             Bb + ((size_t)nb * kbt + kb0 + kb) * 64 + li * 4);
    }
}

__device__ __forceinline__ void gemm_main(const float* __restrict__ Ab, int ka,
                                          const float* __restrict__ Bb, int kbt,
                                          int kIters, float acc[4][4][4])
{
    extern __shared__ float smem[];
    const int wid  = threadIdx.x >> 5;
    const int lane = threadIdx.x & 31;

    #pragma unroll
    for (int s = 0; s < NSTAGES - 1; s++) {
        load_stage(smem + s * STAGE_F, Ab, ka, Bb, kbt, s * 4);
        CP_COMMIT();
    }

    int slot = 0;
    for (int it = 0; it < kIters; it++) {
        CP_WAIT1();
        __syncthreads();

        const int nk = it + NSTAGES - 1;
        if (nk < kIters) {
            int ns = nk % NSTAGES;
            load_stage(smem + ns * STAGE_F, Ab, ka, Bb, kbt, nk * 4);
        }
        CP_COMMIT();

        const float* sA = smem + slot * STAGE_F + ((wid >> 2) * 4) * 512;
        const float* sB = smem + slot * STAGE_F + 4096 + ((wid & 3) * 4) * 256;

        #pragma unroll
        for (int ks = 0; ks < 4; ks++) {
            float4 av[4];
            #pragma unroll
            for (int mf = 0; mf < 4; mf++)
                av[mf] = *reinterpret_cast<const float4*>(sA + mf * 512 + ks * 128 + lane * 4);
            float2 bv[4];
            #pragma unroll
            for (int nf = 0; nf < 4; nf++)
                bv[nf] = *reinterpret_cast<const float2*>(sB + nf * 256 + ks * 64 + lane * 2);
            #pragma unroll
            for (int mf = 0; mf < 4; mf++)
                #pragma unroll
                for (int nf = 0; nf < 4; nf++)
                    mma8(acc[mf][nf], av[mf], bv[nf]);
        }
        if (++slot == NSTAGES) slot = 0;
    }
}

#define ZERO_ACC(acc) do { \
    _Pragma("unroll") for (int _i = 0; _i < 4; _i++) \
    _Pragma("unroll") for (int _j = 0; _j < 4; _j++) \
    _Pragma("unroll") for (int _l = 0; _l < 4; _l++) acc[_i][_j][_l] = 0.0f; \
} while (0)

// epilogue coordinates: warp (wid>>2) m-half, (wid&3) n-quarter
#define EPI_COORDS() \
    const int wid = threadIdx.x >> 5, lane = threadIdx.x & 31; \
    const int g = lane >> 2, tg = lane & 3; \
    const int rb = ((wid >> 2) << 6) + g; \
    const int cb = ((wid & 3) << 5) + 2 * tg

// ---------------- GEMM kernels ----------------------------------------------
__global__ __launch_bounds__(256, 2)
void proj_kernel()
{
    const int z  = blockIdx.z;
    const int m0 = blockIdx.y * BM;          // global row 0..8191
    const int n0 = blockIdx.x * BN;          // 0..1023
    const float* Ab = g_PAX + ((size_t)(m0 >> 4) * 128) * 128;
    const float* Bb = g_PBW + ((size_t)(z * 128 + (n0 >> 3)) * 128) * 64;

    float acc[4][4][4];
    ZERO_ACC(acc);
    gemm_main(Ab, 128, Bb, 128, DIM / BK, acc);

    EPI_COORDS();
    const int b = m0 >> 11;
    const int rbg = m0 + rb, cbg = n0 + cb;

    if (z == 0) {
        float* base = g_PAQ + (size_t)b * (128 * 128 * 128);
        #pragma unroll
        for (int mf = 0; mf < 4; mf++)
            #pragma unroll
            for (int nf = 0; nf < 4; nf++) {
                const int r = (rbg + mf * 16) & 2047, c = cbg + nf * 8;
                base[paIdx(128, r,     c    )] = rna_tf32(acc[mf][nf][0]);
                base[paIdx(128, r,     c + 1)] = rna_tf32(acc[mf][nf][1]);
                base[paIdx(128, r + 8, c    )] = rna_tf32(acc[mf][nf][2]);
                base[paIdx(128, r + 8, c + 1)] = rna_tf32(acc[mf][nf][3]);
            }
    } else if (z == 1) {
        float* base = g_PBK + (size_t)b * (256 * 128 * 64);
        #pragma unroll
        for (int mf = 0; mf < 4; mf++)
            #pragma unroll
            for (int nf = 0; nf < 4; nf++) {
                const int r = (rbg + mf * 16) & 2047, c = cbg + nf * 8;
                base[pbIdx(128, r,     c    )] = rna_tf32(acc[mf][nf][0]);
                base[pbIdx(128, r,     c + 1)] = rna_tf32(acc[mf][nf][1]);
                base[pbIdx(128, r + 8, c    )] = rna_tf32(acc[mf][nf][2]);
                base[pbIdx(128, r + 8, c + 1)] = rna_tf32(acc[mf][nf][3]);
            }
    } else {
        // V: write directly in packed-B(V^T) layout: n=dim col, k=seq row
        float* base = g_PBV + (size_t)b * (128 * 256 * 64);
        #pragma unroll
        for (int mf = 0; mf < 4; mf++)
            #pragma unroll
            for (int nf = 0; nf < 4; nf++) {
                const int r = (rbg + mf * 16) & 2047, c = cbg + nf * 8;
                base[pbIdx(256, c,     r    )] = rna_tf32(acc[mf][nf][0]);
                base[pbIdx(256, c + 1, r    )] = rna_tf32(acc[mf][nf][1]);
                base[pbIdx(256, c,     r + 8)] = rna_tf32(acc[mf][nf][2]);
                base[pbIdx(256, c + 1, r + 8)] = rna_tf32(acc[mf][nf][3]);
            }
    }
}

__global__ __launch_bounds__(256, 2)
void qk_kernel()
{
    const int b  = blockIdx.z;
    const int q0 = blockIdx.y * BM;
    const int k0 = blockIdx.x * BN;
    if (k0 > q0) return;

    const float* Ab = g_PAQ + (size_t)b * (128*128*128) + ((size_t)(q0 >> 4) * 128) * 128;
    const float* Bb = g_PBK + (size_t)b * (256*128*64)  + ((size_t)(k0 >> 3) * 128) * 64;

    float acc[4][4][4];
    ZERO_ACC(acc);
    gemm_main(Ab, 128, Bb, 128, DIM / BK, acc);

    float* base = g_PAS + (size_t)b * (128 * 256 * 128);
    const float scale = 0.03125f;
    EPI_COORDS();
    const int rbg = q0 + rb, cbg = k0 + cb;
    #pragma unroll
    for (int mf = 0; mf < 4; mf++)
        #pragma unroll
        for (int nf = 0; nf < 4; nf++) {
            const int r0 = rbg + mf * 16, r1 = r0 + 8;
            const int c  = cbg + nf * 8;
            base[paIdx(256, r0, c    )] = (c     <= r0) ? acc[mf][nf][0] * scale : -CUDART_INF_F;
            base[paIdx(256, r0, c + 1)] = (c + 1 <= r0) ? acc[mf][nf][1] * scale : -CUDART_INF_F;
            base[paIdx(256, r1, c    )] = (c     <= r1) ? acc[mf][nf][2] * scale : -CUDART_INF_F;
            base[paIdx(256, r1, c + 1)] = (c + 1 <= r1) ? acc[mf][nf][3] * scale : -CUDART_INF_F;
        }
}

__global__ __launch_bounds__(256, 2)
void pv_kernel(float* __restrict__ out)
{
    const int b  = blockIdx.z;
    const int q0 = blockIdx.y * BM;
    const int n0 = blockIdx.x * BN;

    const float* Ab = g_PAS + (size_t)b * (128*256*128) + ((size_t)(q0 >> 4) * 256) * 128;
    const float* Bb = g_PBV + (size_t)b * (128*256*64)  + ((size_t)(n0 >> 3) * 256) * 64;

    float acc[4][4][4];
    ZERO_ACC(acc);
    gemm_main(Ab, 256, Bb, 256, (q0 + BM) / BK, acc);

    float* O = out + (size_t)b * SEQ * DIM;
    EPI_COORDS();
    const int rbg = q0 + rb, cbg = n0 + cb;
    #pragma unroll
    for (int mf = 0; mf < 4; mf++)
        #pragma unroll
        for (int nf = 0; nf < 4; nf++) {
            float* p0 = O + (size_t)(rbg + mf * 16) * DIM + cbg + nf * 8;
            float* p1 = O + (size_t)(rbg + mf * 16 + 8) * DIM + cbg + nf * 8;
            *reinterpret_cast<float2*>(p0) = make_float2(acc[mf][nf][0], acc[mf][nf][1]);
            *reinterpret_cast<float2*>(p1) = make_float2(acc[mf][nf][2], acc[mf][nf][3]);
        }
}

// ---------------- pack kernels ----------------------------------------------
__global__ __launch_bounds__(256)
void pack_x_kernel(const float* __restrict__ x)
{
    __shared__ float sm[16][260];
    const int mb = blockIdx.x;              // 0..511 (16-row group of 8192)
    const int kc = blockIdx.y;              // 0..3 (256-col chunk)
    const float* src = x + (size_t)mb * 16 * DIM + kc * 256;
    for (int i = threadIdx.x; i < 1024; i += 256) {   // 16x256 floats as float4
        int row = i >> 6, c4 = i & 63;
        float4 v = *reinterpret_cast<const float4*>(src + (size_t)row * DIM + c4 * 4);
        *reinterpret_cast<float4*>(&sm[row][c4 * 4]) = v;
    }
    __syncthreads();
    #pragma unroll
    for (int j = 0; j < 4; j++) {
        int s = threadIdx.x + j * 256;      // 0..1023 = 32 kblk x 32 lanes
        int kbl = s >> 5, L = s & 31;
        int r8 = L >> 2, c4 = L & 3;
        float4 v;
        v.x = rna_tf32(sm[r8    ][kbl * 8 + c4    ]);
        v.y = rna_tf32(sm[r8 + 8][kbl * 8 + c4    ]);
        v.z = rna_tf32(sm[r8    ][kbl * 8 + c4 + 4]);
        v.w = rna_tf32(sm[r8 + 8][kbl * 8 + c4 + 4]);
        *reinterpret_cast<float4*>(
            g_PAX + ((size_t)(mb * 128 + kc * 32 + kbl)) * 128 + L * 4) = v;
    }
}

__global__ __launch_bounds__(256)
void pack_w_kernel(const float* __restrict__ Wq,
                   const float* __restrict__ Wk,
                   const float* __restrict__ Wv)
{
    int s = blockIdx.x * 256 + threadIdx.x;
    int L = s & 31, kblk = (s >> 5) & 127, nblk = (s >> 12) & 127, z = s >> 19;
    const float* W = (z == 0) ? Wq : (z == 1) ? Wk : Wv;
    int n = nblk * 8 + (L >> 2), k = kblk * 8 + (L & 3);
    float2 v;
    v.x = rna_tf32(W[(size_t)k * DIM + n]);
    v.y = rna_tf32(W[(size_t)(k + 4) * DIM + n]);
    *reinterpret_cast<float2*>(
        g_PBW + ((size_t)((z * 128 + nblk) * 128 + kblk)) * 64 + L * 2) = v;
}

// ---------------- softmax on packed layout ----------------------------------
__global__ __launch_bounds__(256)
void softmax_kernel()
{
    const int mblk = blockIdx.x;            // 0..127
    const int b    = blockIdx.y;
    float* base = g_PAS + (size_t)b * (128 * 256 * 128) + (size_t)mblk * 256 * 128;
    const int KB = 2 * mblk + 2;                     // blocks holding k <= m0+15
    const int ZB = ((mblk >> 3) << 4) + 16;          // causal boundary blocks

    const int t = threadIdx.x, kp = t >> 5, lane = t & 31;
    const int r0 = lane >> 2;
    __shared__ float red[16][33];
    __shared__ float rowmax[16], rowinv[16];

    float mlo = -CUDART_INF_F, mhi = -CUDART_INF_F;
    for (int kb = kp; kb < KB; kb += 8) {
        float4 f = *reinterpret_cast<const float4*>(base + kb * 128 + lane * 4);
        mlo = fmaxf(mlo, fmaxf(f.x, f.z));
        mhi = fmaxf(mhi, fmaxf(f.y, f.w));
    }
    red[r0][kp * 4 + (lane & 3)] = mlo;
    red[r0 + 8][kp * 4 + (lane & 3)] = mhi;
    __syncthreads();
    if (t < 16) {
        float m = -CUDART_INF_F;
        #pragma unroll
        for (int j = 0; j < 32; j++) m = fmaxf(m, red[t][j]);
        rowmax[t] = m;
    }
    __syncthreads();
    const float Mlo = rowmax[r0], Mhi = rowmax[r0 + 8];

    float slo = 0.0f, shi = 0.0f;
    for (int kb = kp; kb < KB; kb += 8) {
        float4 f = *reinterpret_cast<const float4*>(base + kb * 128 + lane * 4);
        slo += __expf(f.x - Mlo) + __expf(f.z - Mlo);
        shi += __expf(f.y - Mhi) + __expf(f.w - Mhi);
    }
    __syncthreads();
    red[r0][kp * 4 + (lane & 3)] = slo;
    red[r0 + 8][kp * 4 + (lane & 3)] = shi;
    __syncthreads();
    if (t < 16) {
        float ssum = 0.0f;
        #pragma unroll
        for (int j = 0; j < 32; j++) ssum += red[t][j];
        rowinv[t] = 1.0f / ssum;
    }
    __syncthreads();
    const float Ilo = rowinv[r0], Ihi = rowinv[r0 + 8];

    for (int kb = kp; kb < KB; kb += 8) {
        float4 f = *reinterpret_cast<float4*>(base + kb * 128 + lane * 4);
        f.x = rna_tf32(__expf(f.x - Mlo) * Ilo);
        f.z = rna_tf32(__expf(f.z - Mlo) * Ilo);
        f.y = rna_tf32(__expf(f.y - Mhi) * Ihi);
        f.w = rna_tf32(__expf(f.w - Mhi) * Ihi);
        *reinterpret_cast<float4*>(base + kb * 128 + lane * 4) = f;
    }

    // zero the masked blocks [KB, ZB) (read dense by PV)
    const int nz4 = (ZB - KB) * 32;
    float4 z4 = make_float4(0.f, 0.f, 0.f, 0.f);
    for (int i = t; i < nz4; i += 256)
        reinterpret_cast<float4*>(base + KB * 128)[i] = z4;
}

// ---------------- host side --------------------------------------------------
extern "C" void kernel_launch(void* const* d_in, const int* in_sizes, int n_in,
                              void* d_out, int out_size)
{
    const float* x  = (const float*)d_in[0];
    const float* Wq = (const float*)d_in[1];
    const float* Wk = (const float*)d_in[2];
    const float* Wv = (const float*)d_in[3];
    float* out = (float*)d_out;

    static bool configured = false;
    if (!configured) {
        cudaFuncSetAttribute(proj_kernel, cudaFuncAttributeMaxDynamicSharedMemorySize, SMEM_BYTES);
        cudaFuncSetAttribute(qk_kernel,   cudaFuncAttributeMaxDynamicSharedMemorySize, SMEM_BYTES);
        cudaFuncSetAttribute(pv_kernel,   cudaFuncAttributeMaxDynamicSharedMemorySize, SMEM_BYTES);
        configured = true;
    }

    pack_x_kernel<<<dim3(512, 4), 256>>>(x);
    pack_w_kernel<<<6144, 256>>>(Wq, Wk, Wv);
    proj_kernel<<<dim3(DIM / BN, MROWS / BM, 3), 256, SMEM_BYTES>>>();
    qk_kernel<<<dim3(SEQ / BN, SEQ / BM, BATCH), 256, SMEM_BYTES>>>();   // profiled idx 3
    softmax_kernel<<<dim3(128, BATCH), 256>>>();
    pv_kernel<<<dim3(DIM / BN, SEQ / BM, BATCH), 256, SMEM_BYTES>>>(out);
}